// round 1
// baseline (speedup 1.0000x reference)
#include <cuda_runtime.h>
#include <cuda_fp16.h>
#include <cstdint>
#include <cstddef>

#define TT 2048   // tokens
#define HH 1024   // hidden
#define FF 2048   // ffn
#define EE 8      // experts

// ---------------- static device scratch (allocation-free rule) ----------------
static __device__ __half g_xh[TT * HH];                          // 4 MB
static __device__ __half g_w1h[(size_t)EE * FF * HH];            // 32 MB
static __device__ __half g_v1h[(size_t)EE * FF * HH];            // 32 MB
static __device__ __half g_w2h[(size_t)EE * FF * HH];            // 32 MB
static __device__ __half g_inter[(size_t)EE * TT * FF];          // 64 MB
static __device__ int    g_cnt[EE];
static __device__ int    g_tok[EE * TT];
static __device__ float  g_cw[EE * TT];
static __device__ int    g_is64;

// ---------------- small helpers ----------------
__device__ __forceinline__ void cp_async16(void* sdst, const void* gsrc, bool pred) {
    unsigned s = (unsigned)__cvta_generic_to_shared(sdst);
    int sz = pred ? 16 : 0;
    asm volatile("cp.async.cg.shared.global [%0], [%1], 16, %2;\n" :: "r"(s), "l"(gsrc), "r"(sz));
}
__device__ __forceinline__ void cp_commit() { asm volatile("cp.async.commit_group;\n"); }
template <int N>
__device__ __forceinline__ void cp_wait() { asm volatile("cp.async.wait_group %0;\n" :: "n"(N)); }

__device__ __forceinline__ void mma16816(float* c, const uint32_t* a, const uint32_t* b) {
    asm volatile(
        "mma.sync.aligned.m16n8k16.row.col.f32.f16.f16.f32 "
        "{%0,%1,%2,%3}, {%4,%5,%6,%7}, {%8,%9}, {%0,%1,%2,%3};\n"
        : "+f"(c[0]), "+f"(c[1]), "+f"(c[2]), "+f"(c[3])
        : "r"(a[0]), "r"(a[1]), "r"(a[2]), "r"(a[3]), "r"(b[0]), "r"(b[1]));
}

// ---------------- prep kernels ----------------
// Detect whether top_experts is int64 (odd 32-bit words all zero) + zero counts.
__global__ void detect_zero_kernel(const unsigned int* __restrict__ te) {
    __shared__ unsigned acc;
    if (threadIdx.x == 0) acc = 0u;
    if (threadIdx.x < EE) g_cnt[threadIdx.x] = 0;
    __syncthreads();
    unsigned v = 0;
    for (int j = threadIdx.x; j < 2048; j += blockDim.x) v |= te[2 * j + 1];
    atomicOr(&acc, v);
    __syncthreads();
    if (threadIdx.x == 0) g_is64 = (acc == 0u) ? 1 : 0;
}

// Build per-expert token lists + combined weights (sums duplicate expert slots).
__global__ void gather_kernel(const float* __restrict__ tw, const int* __restrict__ te32) {
    int t = blockIdx.x * blockDim.x + threadIdx.x;
    if (t >= TT) return;
    int e0, e1;
    if (g_is64) { e0 = te32[4 * t]; e1 = te32[4 * t + 2]; }
    else        { e0 = te32[2 * t]; e1 = te32[2 * t + 1]; }
    float w0 = tw[2 * t], w1 = tw[2 * t + 1];
    if (e0 == e1) {
        int p = atomicAdd(&g_cnt[e0], 1);
        g_tok[e0 * TT + p] = t; g_cw[e0 * TT + p] = w0 + w1;
    } else {
        int p0 = atomicAdd(&g_cnt[e0], 1);
        g_tok[e0 * TT + p0] = t; g_cw[e0 * TT + p0] = w0;
        int p1 = atomicAdd(&g_cnt[e1], 1);
        g_tok[e1 * TT + p1] = t; g_cw[e1 * TT + p1] = w1;
    }
}

__global__ void convert_kernel(const float4* __restrict__ src, __half2* __restrict__ dst, int n4) {
    int i = blockIdx.x * blockDim.x + threadIdx.x;
    if (i < n4) {
        float4 f = src[i];
        dst[2 * i]     = __floats2half2_rn(f.x, f.y);
        dst[2 * i + 1] = __floats2half2_rn(f.z, f.w);
    }
}

__global__ void zero_kernel(float4* __restrict__ o, int n4) {
    int i = blockIdx.x * blockDim.x + threadIdx.x;
    if (i < n4) o[i] = make_float4(0.f, 0.f, 0.f, 0.f);
}

// ---------------- GEMM1: gate/up fused (A gathered x, B = w1 & v1), SiLU*up epilogue ----------------
// BM=128, BN=64, BK=32. 256 threads = 8 warps (4 M x 2 N). Warp tile 32x32 per B-matrix.
__global__ __launch_bounds__(256) void gemm1_kernel() {
    const int e  = blockIdx.z;
    const int M  = g_cnt[e];
    const int m0 = blockIdx.y * 128;
    if (m0 >= M) return;
    const int n0 = blockIdx.x * 64;

    __shared__ __half As[2][128 * 40];
    __shared__ __half Bw[2][64 * 40];
    __shared__ __half Bv[2][64 * 40];

    const int tid = threadIdx.x;

    // A-load assignment (two 16B chunks per thread per stage), tokens preloaded once
    int    rowA[2]; size_t aoff[2]; bool apred[2];
#pragma unroll
    for (int it = 0; it < 2; it++) {
        int idx = tid + it * 256;
        rowA[it] = idx >> 2;
        int gr = m0 + rowA[it];
        apred[it] = (gr < M);
        aoff[it] = apred[it] ? (size_t)g_tok[e * TT + gr] * HH : 0;
    }
    const int kcA = (tid & 3) * 8;
    const int rowB = tid >> 2;
    const int kcB  = (tid & 3) * 8;
    const size_t boff = ((size_t)e * FF + n0 + rowB) * HH;

    auto load_stage = [&](int s, int kt) {
        int k0 = kt * 32;
#pragma unroll
        for (int it = 0; it < 2; it++)
            cp_async16(&As[s][rowA[it] * 40 + kcA], g_xh + aoff[it] + k0 + kcA, apred[it]);
        cp_async16(&Bw[s][rowB * 40 + kcB], g_w1h + boff + k0 + kcB, true);
        cp_async16(&Bv[s][rowB * 40 + kcB], g_v1h + boff + k0 + kcB, true);
    };

    const int wid = tid >> 5, lane = tid & 31;
    const int wm = wid >> 1, wn = wid & 1;
    const int g = lane >> 2, tg = lane & 3;

    float cg[2][4][4] = {}, cu[2][4][4] = {};

    load_stage(0, 0); cp_commit();
    const int nk = HH / 32;
    for (int kt = 0; kt < nk; kt++) {
        int s = kt & 1;
        if (kt + 1 < nk) { load_stage(s ^ 1, kt + 1); cp_commit(); cp_wait<1>(); }
        else             { cp_wait<0>(); }
        __syncthreads();
#pragma unroll
        for (int k16 = 0; k16 < 32; k16 += 16) {
            uint32_t a[2][4];
#pragma unroll
            for (int mi = 0; mi < 2; mi++) {
                int rm = wm * 32 + mi * 16;
                const __half* base = &As[s][0];
                a[mi][0] = *(const uint32_t*)(base + (rm + g)     * 40 + k16 + 2 * tg);
                a[mi][1] = *(const uint32_t*)(base + (rm + g + 8) * 40 + k16 + 2 * tg);
                a[mi][2] = *(const uint32_t*)(base + (rm + g)     * 40 + k16 + 2 * tg + 8);
                a[mi][3] = *(const uint32_t*)(base + (rm + g + 8) * 40 + k16 + 2 * tg + 8);
            }
            uint32_t bw[4][2], bv[4][2];
#pragma unroll
            for (int ni = 0; ni < 4; ni++) {
                int nr = wn * 32 + ni * 8 + g;
                bw[ni][0] = *(const uint32_t*)(&Bw[s][nr * 40 + k16 + 2 * tg]);
                bw[ni][1] = *(const uint32_t*)(&Bw[s][nr * 40 + k16 + 2 * tg + 8]);
                bv[ni][0] = *(const uint32_t*)(&Bv[s][nr * 40 + k16 + 2 * tg]);
                bv[ni][1] = *(const uint32_t*)(&Bv[s][nr * 40 + k16 + 2 * tg + 8]);
            }
#pragma unroll
            for (int mi = 0; mi < 2; mi++)
#pragma unroll
                for (int ni = 0; ni < 4; ni++) {
                    mma16816(cg[mi][ni], a[mi], bw[ni]);
                    mma16816(cu[mi][ni], a[mi], bv[ni]);
                }
        }
        __syncthreads();
    }

    // epilogue: inter = silu(gate) * up, fp16 store by slot row
#pragma unroll
    for (int mi = 0; mi < 2; mi++) {
        int rbase = m0 + wm * 32 + mi * 16 + g;
#pragma unroll
        for (int hlf = 0; hlf < 2; hlf++) {
            int r = rbase + hlf * 8;
            if (r >= M) continue;
            size_t ro = ((size_t)e * TT + r) * FF;
#pragma unroll
            for (int ni = 0; ni < 4; ni++) {
                int c = n0 + wn * 32 + ni * 8 + 2 * tg;
                float g0 = cg[mi][ni][hlf * 2 + 0], g1 = cg[mi][ni][hlf * 2 + 1];
                float u0 = cu[mi][ni][hlf * 2 + 0], u1 = cu[mi][ni][hlf * 2 + 1];
                float h0 = g0 / (1.f + __expf(-g0)) * u0;
                float h1 = g1 / (1.f + __expf(-g1)) * u1;
                *(__half2*)&g_inter[ro + c] = __floats2half2_rn(h0, h1);
            }
        }
    }
}

// ---------------- GEMM2: down-proj (A = inter, B = w2 [F,H]) + weighted scatter ----------------
__global__ __launch_bounds__(256) void gemm2_kernel(float* __restrict__ out) {
    const int e  = blockIdx.z;
    const int M  = g_cnt[e];
    const int m0 = blockIdx.y * 128;
    if (m0 >= M) return;
    const int n0 = blockIdx.x * 64;

    __shared__ __half As[2][128 * 40];
    __shared__ __half Bs[2][32 * 72];   // [k][n] layout, pad 8

    const int tid = threadIdx.x;
    // A: row=idx>>2, kc=(idx&3)*8 ; rows beyond M read zeros (never-written scratch)
    int rowA[2];
#pragma unroll
    for (int it = 0; it < 2; it++) rowA[it] = (tid + it * 256) >> 2;
    const int kcA = (tid & 3) * 8;
    const size_t abase = ((size_t)e * TT + m0) * FF;
    // B: row(k)=tid>>3 (0..31), hc=(tid&7)*8
    const int rowBk = tid >> 3;
    const int hcB   = (tid & 7) * 8;
    const size_t bbase = ((size_t)e * FF) * HH + n0;

    auto load_stage = [&](int s, int kt) {
        int k0 = kt * 32;
#pragma unroll
        for (int it = 0; it < 2; it++)
            cp_async16(&As[s][rowA[it] * 40 + kcA], g_inter + abase + (size_t)rowA[it] * FF + k0 + kcA, true);
        cp_async16(&Bs[s][rowBk * 72 + hcB], g_w2h + bbase + (size_t)(k0 + rowBk) * HH + hcB, true);
    };

    const int wid = tid >> 5, lane = tid & 31;
    const int wm = wid >> 1, wn = wid & 1;
    const int g = lane >> 2, tg = lane & 3;

    float c[2][4][4] = {};

    load_stage(0, 0); cp_commit();
    const int nk = FF / 32;
    for (int kt = 0; kt < nk; kt++) {
        int s = kt & 1;
        if (kt + 1 < nk) { load_stage(s ^ 1, kt + 1); cp_commit(); cp_wait<1>(); }
        else             { cp_wait<0>(); }
        __syncthreads();
        const unsigned short* bsp = (const unsigned short*)&Bs[s][0];
#pragma unroll
        for (int k16 = 0; k16 < 32; k16 += 16) {
            uint32_t a[2][4];
#pragma unroll
            for (int mi = 0; mi < 2; mi++) {
                int rm = wm * 32 + mi * 16;
                const __half* base = &As[s][0];
                a[mi][0] = *(const uint32_t*)(base + (rm + g)     * 40 + k16 + 2 * tg);
                a[mi][1] = *(const uint32_t*)(base + (rm + g + 8) * 40 + k16 + 2 * tg);
                a[mi][2] = *(const uint32_t*)(base + (rm + g)     * 40 + k16 + 2 * tg + 8);
                a[mi][3] = *(const uint32_t*)(base + (rm + g + 8) * 40 + k16 + 2 * tg + 8);
            }
            uint32_t b[4][2];
#pragma unroll
            for (int ni = 0; ni < 4; ni++) {
                int nc = wn * 32 + ni * 8 + g;
                int kr = k16 + 2 * tg;
                unsigned x0 = bsp[(kr)     * 72 + nc];
                unsigned x1 = bsp[(kr + 1) * 72 + nc];
                unsigned x2 = bsp[(kr + 8) * 72 + nc];
                unsigned x3 = bsp[(kr + 9) * 72 + nc];
                b[ni][0] = x0 | (x1 << 16);
                b[ni][1] = x2 | (x3 << 16);
            }
#pragma unroll
            for (int mi = 0; mi < 2; mi++)
#pragma unroll
                for (int ni = 0; ni < 4; ni++)
                    mma16816(c[mi][ni], a[mi], b[ni]);
        }
        __syncthreads();
    }

    // epilogue: out[token] += cw * down
#pragma unroll
    for (int mi = 0; mi < 2; mi++) {
        int rbase = m0 + wm * 32 + mi * 16 + g;
#pragma unroll
        for (int hlf = 0; hlf < 2; hlf++) {
            int r = rbase + hlf * 8;
            if (r >= M) continue;
            int   t = g_tok[e * TT + r];
            float w = g_cw[e * TT + r];
            float* orow = out + (size_t)t * HH;
#pragma unroll
            for (int ni = 0; ni < 4; ni++) {
                int h = n0 + wn * 32 + ni * 8 + 2 * tg;
                atomicAdd(&orow[h],     w * c[mi][ni][hlf * 2 + 0]);
                atomicAdd(&orow[h + 1], w * c[mi][ni][hlf * 2 + 1]);
            }
        }
    }
}

// ---------------- launch ----------------
extern "C" void kernel_launch(void* const* d_in, const int* in_sizes, int n_in,
                              void* d_out, int out_size) {
    const float* x  = (const float*)d_in[0];
    // d_in[1] = router probs, unused by reference
    const float* tw = (const float*)d_in[2];
    const void*  te = d_in[3];
    const float* w1 = (const float*)d_in[4];
    const float* v1 = (const float*)d_in[5];
    const float* w2 = (const float*)d_in[6];
    float* out = (float*)d_out;

    void *pxh, *pw1, *pv1, *pw2;
    cudaGetSymbolAddress(&pxh, g_xh);
    cudaGetSymbolAddress(&pw1, g_w1h);
    cudaGetSymbolAddress(&pv1, g_v1h);
    cudaGetSymbolAddress(&pw2, g_w2h);

    detect_zero_kernel<<<1, 256>>>((const unsigned int*)te);
    gather_kernel<<<TT / 256, 256>>>(tw, (const int*)te);

    const int nW4 = (EE * FF * HH) / 4;   // 4,194,304
    convert_kernel<<<nW4 / 256, 256>>>((const float4*)w1, (__half2*)pw1, nW4);
    convert_kernel<<<nW4 / 256, 256>>>((const float4*)v1, (__half2*)pv1, nW4);
    convert_kernel<<<nW4 / 256, 256>>>((const float4*)w2, (__half2*)pw2, nW4);
    const int nX4 = (TT * HH) / 4;
    convert_kernel<<<nX4 / 256, 256>>>((const float4*)x, (__half2*)pxh, nX4);

    zero_kernel<<<(out_size / 4 + 255) / 256, 256>>>((float4*)d_out, out_size / 4);

    gemm1_kernel<<<dim3(FF / 64, TT / 128, EE), 256>>>();
    gemm2_kernel<<<dim3(HH / 64, TT / 128, EE), 256>>>(out);
}

// round 2
// speedup vs baseline: 1.0650x; 1.0650x over previous
#include <cuda_runtime.h>
#include <cuda_fp16.h>
#include <cstdint>
#include <cstddef>

#define TT 2048   // tokens
#define HH 1024   // hidden
#define FF 2048   // ffn
#define EE 8      // experts

// ---------------- static device scratch (allocation-free rule) ----------------
static __device__ __half g_xh[TT * HH];                          // 4 MB
static __device__ __half g_w1h[(size_t)EE * FF * HH];            // 32 MB
static __device__ __half g_v1h[(size_t)EE * FF * HH];            // 32 MB
static __device__ __half g_w2h[(size_t)EE * FF * HH];            // 32 MB
static __device__ __half g_inter[(size_t)EE * TT * FF];          // 64 MB
static __device__ int    g_cnt[EE];
static __device__ int    g_tok[EE * TT];
static __device__ float  g_cw[EE * TT];
static __device__ int    g_is64;

// ---------------- small helpers ----------------
__device__ __forceinline__ void cp_async16(void* sdst, const void* gsrc, bool pred) {
    unsigned s = (unsigned)__cvta_generic_to_shared(sdst);
    int sz = pred ? 16 : 0;
    asm volatile("cp.async.cg.shared.global [%0], [%1], 16, %2;\n" :: "r"(s), "l"(gsrc), "r"(sz));
}
__device__ __forceinline__ void cp_commit() { asm volatile("cp.async.commit_group;\n"); }
template <int N>
__device__ __forceinline__ void cp_wait() { asm volatile("cp.async.wait_group %0;\n" :: "n"(N)); }

__device__ __forceinline__ void mma16816(float* c, const uint32_t* a, const uint32_t* b) {
    asm volatile(
        "mma.sync.aligned.m16n8k16.row.col.f32.f16.f16.f32 "
        "{%0,%1,%2,%3}, {%4,%5,%6,%7}, {%8,%9}, {%0,%1,%2,%3};\n"
        : "+f"(c[0]), "+f"(c[1]), "+f"(c[2]), "+f"(c[3])
        : "r"(a[0]), "r"(a[1]), "r"(a[2]), "r"(a[3]), "r"(b[0]), "r"(b[1]));
}
__device__ __forceinline__ void ldsm_x4(uint32_t* r, uint32_t addr) {
    asm volatile("ldmatrix.sync.aligned.m8n8.x4.shared.b16 {%0,%1,%2,%3}, [%4];\n"
                 : "=r"(r[0]), "=r"(r[1]), "=r"(r[2]), "=r"(r[3]) : "r"(addr));
}
__device__ __forceinline__ void ldsm_x4_t(uint32_t* r, uint32_t addr) {
    asm volatile("ldmatrix.sync.aligned.m8n8.x4.trans.shared.b16 {%0,%1,%2,%3}, [%4];\n"
                 : "=r"(r[0]), "=r"(r[1]), "=r"(r[2]), "=r"(r[3]) : "r"(addr));
}

// ---------------- prep kernels ----------------
__global__ void detect_zero_kernel(const unsigned int* __restrict__ te) {
    __shared__ unsigned acc;
    if (threadIdx.x == 0) acc = 0u;
    if (threadIdx.x < EE) g_cnt[threadIdx.x] = 0;
    __syncthreads();
    unsigned v = 0;
    for (int j = threadIdx.x; j < 2048; j += blockDim.x) v |= te[2 * j + 1];
    atomicOr(&acc, v);
    __syncthreads();
    if (threadIdx.x == 0) g_is64 = (acc == 0u) ? 1 : 0;
}

__global__ void gather_kernel(const float* __restrict__ tw, const int* __restrict__ te32) {
    int t = blockIdx.x * blockDim.x + threadIdx.x;
    if (t >= TT) return;
    int e0, e1;
    if (g_is64) { e0 = te32[4 * t]; e1 = te32[4 * t + 2]; }
    else        { e0 = te32[2 * t]; e1 = te32[2 * t + 1]; }
    float w0 = tw[2 * t], w1 = tw[2 * t + 1];
    if (e0 == e1) {
        int p = atomicAdd(&g_cnt[e0], 1);
        g_tok[e0 * TT + p] = t; g_cw[e0 * TT + p] = w0 + w1;
    } else {
        int p0 = atomicAdd(&g_cnt[e0], 1);
        g_tok[e0 * TT + p0] = t; g_cw[e0 * TT + p0] = w0;
        int p1 = atomicAdd(&g_cnt[e1], 1);
        g_tok[e1 * TT + p1] = t; g_cw[e1 * TT + p1] = w1;
    }
}

__device__ __forceinline__ void cvt_store(__half2* dst, int j, float4 f) {
    __half2 h0 = __floats2half2_rn(f.x, f.y);
    __half2 h1 = __floats2half2_rn(f.z, f.w);
    uint2 u = make_uint2(*(uint32_t*)&h0, *(uint32_t*)&h1);
    *reinterpret_cast<uint2*>(dst + 2 * j) = u;
}

// Fused convert of w1/v1/w2 (n4 is a power of two: 2^22)
__global__ void convertW_kernel(const float4* __restrict__ w1, const float4* __restrict__ v1,
                                const float4* __restrict__ w2,
                                __half2* __restrict__ d1, __half2* __restrict__ d2,
                                __half2* __restrict__ d3, int n4) {
    int i = blockIdx.x * blockDim.x + threadIdx.x;
    int which = i >> 22;
    int j = i & (n4 - 1);
    const float4* s = (which == 0) ? w1 : (which == 1) ? v1 : w2;
    __half2*      d = (which == 0) ? d1 : (which == 1) ? d2 : d3;
    cvt_store(d, j, s[j]);
}

__global__ void convertX_kernel(const float4* __restrict__ src, __half2* __restrict__ dst, int n4) {
    int i = blockIdx.x * blockDim.x + threadIdx.x;
    if (i < n4) cvt_store(dst, i, src[i]);
}

__global__ void zero_kernel(float4* __restrict__ o, int n4) {
    int i = blockIdx.x * blockDim.x + threadIdx.x;
    if (i < n4) o[i] = make_float4(0.f, 0.f, 0.f, 0.f);
}

// ---------------- GEMM1: gate/up fused. BM=128, BN=64 (x2 B-matrices), BK=32 ----------------
// 8 warps (4M x 2N). Warp tile 32x32 per B-matrix. ldmatrix fragment loads.
__global__ __launch_bounds__(256) void gemm1_kernel() {
    const int e  = blockIdx.z;
    const int M  = g_cnt[e];
    const int m0 = blockIdx.y * 128;
    if (m0 >= M) return;
    const int n0 = blockIdx.x * 64;

    __shared__ __half As[2][128 * 40];
    __shared__ __half Bw[2][64 * 40];
    __shared__ __half Bv[2][64 * 40];

    const int tid = threadIdx.x;

    int    rowA[2]; size_t aoff[2]; bool apred[2];
#pragma unroll
    for (int it = 0; it < 2; it++) {
        int idx = tid + it * 256;
        rowA[it] = idx >> 2;
        int gr = m0 + rowA[it];
        apred[it] = (gr < M);
        aoff[it] = apred[it] ? (size_t)g_tok[e * TT + gr] * HH : 0;
    }
    const int kcA = (tid & 3) * 8;
    const int rowB = tid >> 2;
    const int kcB  = (tid & 3) * 8;
    const size_t boff = ((size_t)e * FF + n0 + rowB) * HH;

    auto load_stage = [&](int s, int kt) {
        int k0 = kt * 32;
#pragma unroll
        for (int it = 0; it < 2; it++)
            cp_async16(&As[s][rowA[it] * 40 + kcA], g_xh + aoff[it] + k0 + kcA, apred[it]);
        cp_async16(&Bw[s][rowB * 40 + kcB], g_w1h + boff + k0 + kcB, true);
        cp_async16(&Bv[s][rowB * 40 + kcB], g_v1h + boff + k0 + kcB, true);
    };

    const int wid = tid >> 5, lane = tid & 31;
    const int wm = wid >> 1, wn = wid & 1;
    const int g = lane >> 2, tg = lane & 3;

    // ldmatrix per-lane offsets (half units)
    const int aOff = (lane & 15) * 40 + (lane >> 4) * 8;                         // + (wm*32+mi*16)*40 + k16
    const int bOff = (((lane >> 4) << 3) + (lane & 7)) * 40 + ((lane >> 3) & 1) * 8; // + (wn*32+p*16)*40 + k16

    const uint32_t sA  = (uint32_t)__cvta_generic_to_shared(&As[0][0]);
    const uint32_t sBw = (uint32_t)__cvta_generic_to_shared(&Bw[0][0]);
    const uint32_t sBv = (uint32_t)__cvta_generic_to_shared(&Bv[0][0]);

    float cg[2][4][4] = {}, cu[2][4][4] = {};

    load_stage(0, 0); cp_commit();
    const int nk = HH / 32;
    for (int kt = 0; kt < nk; kt++) {
        int s = kt & 1;
        if (kt + 1 < nk) { load_stage(s ^ 1, kt + 1); cp_commit(); cp_wait<1>(); }
        else             { cp_wait<0>(); }
        __syncthreads();
        const uint32_t sAs  = sA  + s * (128 * 40 * 2);
        const uint32_t sBws = sBw + s * (64 * 40 * 2);
        const uint32_t sBvs = sBv + s * (64 * 40 * 2);
#pragma unroll
        for (int k16 = 0; k16 < 32; k16 += 16) {
            uint32_t a[2][4];
            ldsm_x4(a[0], sAs + 2 * ((wm * 32)      * 40 + k16 + aOff));
            ldsm_x4(a[1], sAs + 2 * ((wm * 32 + 16) * 40 + k16 + aOff));
            uint32_t bw[4][2], bv[4][2];
#pragma unroll
            for (int p = 0; p < 2; p++) {
                uint32_t r[4];
                ldsm_x4(r, sBws + 2 * ((wn * 32 + p * 16) * 40 + k16 + bOff));
                bw[2*p][0] = r[0]; bw[2*p][1] = r[1]; bw[2*p+1][0] = r[2]; bw[2*p+1][1] = r[3];
                ldsm_x4(r, sBvs + 2 * ((wn * 32 + p * 16) * 40 + k16 + bOff));
                bv[2*p][0] = r[0]; bv[2*p][1] = r[1]; bv[2*p+1][0] = r[2]; bv[2*p+1][1] = r[3];
            }
#pragma unroll
            for (int mi = 0; mi < 2; mi++)
#pragma unroll
                for (int ni = 0; ni < 4; ni++) {
                    mma16816(cg[mi][ni], a[mi], bw[ni]);
                    mma16816(cu[mi][ni], a[mi], bv[ni]);
                }
        }
        __syncthreads();
    }

    // epilogue: inter = silu(gate) * up
#pragma unroll
    for (int mi = 0; mi < 2; mi++) {
        int rbase = m0 + wm * 32 + mi * 16 + g;
#pragma unroll
        for (int hlf = 0; hlf < 2; hlf++) {
            int r = rbase + hlf * 8;
            if (r >= M) continue;
            size_t ro = ((size_t)e * TT + r) * FF;
#pragma unroll
            for (int ni = 0; ni < 4; ni++) {
                int c = n0 + wn * 32 + ni * 8 + 2 * tg;
                float g0 = cg[mi][ni][hlf * 2 + 0], g1 = cg[mi][ni][hlf * 2 + 1];
                float u0 = cu[mi][ni][hlf * 2 + 0], u1 = cu[mi][ni][hlf * 2 + 1];
                float h0 = g0 / (1.f + __expf(-g0)) * u0;
                float h1 = g1 / (1.f + __expf(-g1)) * u1;
                *(__half2*)&g_inter[ro + c] = __floats2half2_rn(h0, h1);
            }
        }
    }
}

// ---------------- GEMM2: down-proj. BM=128, BN=128, BK=32 + weighted scatter ----------------
// 8 warps (4M x 2N). Warp tile 32x64. B via ldmatrix.trans from [k][n] smem.
#define B2S 136   // Bs row stride in halves (128 + 8 pad)
__global__ __launch_bounds__(256) void gemm2_kernel(float* __restrict__ out) {
    const int e  = blockIdx.z;
    const int M  = g_cnt[e];
    const int m0 = blockIdx.y * 128;
    if (m0 >= M) return;
    const int n0 = blockIdx.x * 128;

    __shared__ __half As[2][128 * 40];
    __shared__ __half Bs[2][32 * B2S];

    const int tid = threadIdx.x;
    int rowA[2];
#pragma unroll
    for (int it = 0; it < 2; it++) rowA[it] = (tid + it * 256) >> 2;
    const int kcA = (tid & 3) * 8;
    const size_t abase = ((size_t)e * TT + m0) * FF;
    // B: 512 chunks of 16B per stage (32 k-rows x 16 chunks)
    const size_t bbase = (size_t)e * FF * HH + n0;

    auto load_stage = [&](int s, int kt) {
        int k0 = kt * 32;
#pragma unroll
        for (int it = 0; it < 2; it++)
            cp_async16(&As[s][rowA[it] * 40 + kcA], g_inter + abase + (size_t)rowA[it] * FF + k0 + kcA, true);
#pragma unroll
        for (int it = 0; it < 2; it++) {
            int c = tid + it * 256;
            int kr = c >> 4, nc = (c & 15) * 8;
            cp_async16(&Bs[s][kr * B2S + nc], g_w2h + bbase + (size_t)(k0 + kr) * HH + nc, true);
        }
    };

    const int wid = tid >> 5, lane = tid & 31;
    const int wm = wid >> 1, wn = wid & 1;
    const int g = lane >> 2, tg = lane & 3;

    const int aOff  = (lane & 15) * 40 + (lane >> 4) * 8;
    const int bOffT = ((lane & 7) + ((lane >> 3) & 1) * 8) * B2S + (lane >> 4) * 8; // + k16*B2S + ncw

    const uint32_t sA = (uint32_t)__cvta_generic_to_shared(&As[0][0]);
    const uint32_t sB = (uint32_t)__cvta_generic_to_shared(&Bs[0][0]);

    float c[2][8][4] = {};

    load_stage(0, 0); cp_commit();
    const int nk = FF / 32;
    for (int kt = 0; kt < nk; kt++) {
        int s = kt & 1;
        if (kt + 1 < nk) { load_stage(s ^ 1, kt + 1); cp_commit(); cp_wait<1>(); }
        else             { cp_wait<0>(); }
        __syncthreads();
        const uint32_t sAs = sA + s * (128 * 40 * 2);
        const uint32_t sBs = sB + s * (32 * B2S * 2);
#pragma unroll
        for (int k16 = 0; k16 < 32; k16 += 16) {
            uint32_t a[2][4];
            ldsm_x4(a[0], sAs + 2 * ((wm * 32)      * 40 + k16 + aOff));
            ldsm_x4(a[1], sAs + 2 * ((wm * 32 + 16) * 40 + k16 + aOff));
            uint32_t b[8][2];
#pragma unroll
            for (int p = 0; p < 4; p++) {
                int ncw = wn * 64 + p * 16;
                uint32_t r[4];
                ldsm_x4_t(r, sBs + 2 * (k16 * B2S + ncw + bOffT));
                b[2*p][0] = r[0]; b[2*p][1] = r[1]; b[2*p+1][0] = r[2]; b[2*p+1][1] = r[3];
            }
#pragma unroll
            for (int mi = 0; mi < 2; mi++)
#pragma unroll
                for (int ni = 0; ni < 8; ni++)
                    mma16816(c[mi][ni], a[mi], b[ni]);
        }
        __syncthreads();
    }

    // epilogue: out[token] += cw * down
#pragma unroll
    for (int mi = 0; mi < 2; mi++) {
        int rbase = m0 + wm * 32 + mi * 16 + g;
#pragma unroll
        for (int hlf = 0; hlf < 2; hlf++) {
            int r = rbase + hlf * 8;
            if (r >= M) continue;
            int   t = g_tok[e * TT + r];
            float w = g_cw[e * TT + r];
            float* orow = out + (size_t)t * HH;
#pragma unroll
            for (int ni = 0; ni < 8; ni++) {
                int h = n0 + wn * 64 + ni * 8 + 2 * tg;
                atomicAdd(&orow[h],     w * c[mi][ni][hlf * 2 + 0]);
                atomicAdd(&orow[h + 1], w * c[mi][ni][hlf * 2 + 1]);
            }
        }
    }
}

// ---------------- launch ----------------
extern "C" void kernel_launch(void* const* d_in, const int* in_sizes, int n_in,
                              void* d_out, int out_size) {
    const float* x  = (const float*)d_in[0];
    const float* tw = (const float*)d_in[2];
    const void*  te = d_in[3];
    const float* w1 = (const float*)d_in[4];
    const float* v1 = (const float*)d_in[5];
    const float* w2 = (const float*)d_in[6];
    float* out = (float*)d_out;

    void *pxh, *pw1, *pv1, *pw2;
    cudaGetSymbolAddress(&pxh, g_xh);
    cudaGetSymbolAddress(&pw1, g_w1h);
    cudaGetSymbolAddress(&pv1, g_v1h);
    cudaGetSymbolAddress(&pw2, g_w2h);

    detect_zero_kernel<<<1, 256>>>((const unsigned int*)te);
    gather_kernel<<<TT / 256, 256>>>(tw, (const int*)te);

    const int nW4 = (EE * FF * HH) / 4;   // 4,194,304 = 2^22
    convertW_kernel<<<(3 * nW4) / 256, 256>>>((const float4*)w1, (const float4*)v1, (const float4*)w2,
                                              (__half2*)pw1, (__half2*)pv1, (__half2*)pw2, nW4);
    const int nX4 = (TT * HH) / 4;
    convertX_kernel<<<nX4 / 256, 256>>>((const float4*)x, (__half2*)pxh, nX4);

    zero_kernel<<<(out_size / 4 + 255) / 256, 256>>>((float4*)d_out, out_size / 4);

    gemm1_kernel<<<dim3(FF / 64, TT / 128, EE), 256>>>();
    gemm2_kernel<<<dim3(HH / 128, TT / 128, EE), 256>>>(out);
}

// round 3
// speedup vs baseline: 1.2881x; 1.2095x over previous
#include <cuda_runtime.h>
#include <cuda_fp16.h>
#include <cstdint>
#include <cstddef>

#define TT 2048   // tokens
#define HH 1024   // hidden
#define FF 2048   // ffn
#define EE 8      // experts

// ---------------- static device scratch (allocation-free rule) ----------------
static __device__ __half g_xh[TT * HH];                          // 4 MB
static __device__ __half g_w1h[(size_t)EE * FF * HH];            // 32 MB
static __device__ __half g_v1h[(size_t)EE * FF * HH];            // 32 MB
static __device__ __half g_w2h[(size_t)EE * FF * HH];            // 32 MB
static __device__ __half g_inter[(size_t)EE * TT * FF];          // 64 MB
static __device__ int    g_cnt[EE];
static __device__ int    g_tok[EE * TT];
static __device__ float  g_cw[EE * TT];
static __device__ int    g_is64;

// ---------------- small helpers ----------------
__device__ __forceinline__ void cp_async16(void* sdst, const void* gsrc, bool pred) {
    unsigned s = (unsigned)__cvta_generic_to_shared(sdst);
    int sz = pred ? 16 : 0;
    asm volatile("cp.async.cg.shared.global [%0], [%1], 16, %2;\n" :: "r"(s), "l"(gsrc), "r"(sz));
}
__device__ __forceinline__ void cp_commit() { asm volatile("cp.async.commit_group;\n"); }
template <int N>
__device__ __forceinline__ void cp_wait() { asm volatile("cp.async.wait_group %0;\n" :: "n"(N)); }

__device__ __forceinline__ void mma16816(float* c, const uint32_t* a, const uint32_t* b) {
    asm volatile(
        "mma.sync.aligned.m16n8k16.row.col.f32.f16.f16.f32 "
        "{%0,%1,%2,%3}, {%4,%5,%6,%7}, {%8,%9}, {%0,%1,%2,%3};\n"
        : "+f"(c[0]), "+f"(c[1]), "+f"(c[2]), "+f"(c[3])
        : "r"(a[0]), "r"(a[1]), "r"(a[2]), "r"(a[3]), "r"(b[0]), "r"(b[1]));
}
__device__ __forceinline__ void ldsm_x4(uint32_t* r, uint32_t addr) {
    asm volatile("ldmatrix.sync.aligned.m8n8.x4.shared.b16 {%0,%1,%2,%3}, [%4];\n"
                 : "=r"(r[0]), "=r"(r[1]), "=r"(r[2]), "=r"(r[3]) : "r"(addr));
}
__device__ __forceinline__ void ldsm_x4_t(uint32_t* r, uint32_t addr) {
    asm volatile("ldmatrix.sync.aligned.m8n8.x4.trans.shared.b16 {%0,%1,%2,%3}, [%4];\n"
                 : "=r"(r[0]), "=r"(r[1]), "=r"(r[2]), "=r"(r[3]) : "r"(addr));
}

// ---------------- prep kernels ----------------
__global__ void detect_zero_kernel(const unsigned int* __restrict__ te) {
    __shared__ unsigned acc;
    if (threadIdx.x == 0) acc = 0u;
    if (threadIdx.x < EE) g_cnt[threadIdx.x] = 0;
    __syncthreads();
    unsigned v = 0;
    for (int j = threadIdx.x; j < 2048; j += blockDim.x) v |= te[2 * j + 1];
    atomicOr(&acc, v);
    __syncthreads();
    if (threadIdx.x == 0) g_is64 = (acc == 0u) ? 1 : 0;
}

__global__ void gather_kernel(const float* __restrict__ tw, const int* __restrict__ te32) {
    int t = blockIdx.x * blockDim.x + threadIdx.x;
    if (t >= TT) return;
    int e0, e1;
    if (g_is64) { e0 = te32[4 * t]; e1 = te32[4 * t + 2]; }
    else        { e0 = te32[2 * t]; e1 = te32[2 * t + 1]; }
    float w0 = tw[2 * t], w1 = tw[2 * t + 1];
    if (e0 == e1) {
        int p = atomicAdd(&g_cnt[e0], 1);
        g_tok[e0 * TT + p] = t; g_cw[e0 * TT + p] = w0 + w1;
    } else {
        int p0 = atomicAdd(&g_cnt[e0], 1);
        g_tok[e0 * TT + p0] = t; g_cw[e0 * TT + p0] = w0;
        int p1 = atomicAdd(&g_cnt[e1], 1);
        g_tok[e1 * TT + p1] = t; g_cw[e1 * TT + p1] = w1;
    }
}

__device__ __forceinline__ uint4 pack8(float4 f0, float4 f1) {
    __half2 h0 = __floats2half2_rn(f0.x, f0.y);
    __half2 h1 = __floats2half2_rn(f0.z, f0.w);
    __half2 h2 = __floats2half2_rn(f1.x, f1.y);
    __half2 h3 = __floats2half2_rn(f1.z, f1.w);
    uint4 u;
    u.x = *(uint32_t*)&h0; u.y = *(uint32_t*)&h1;
    u.z = *(uint32_t*)&h2; u.w = *(uint32_t*)&h3;
    return u;
}

// Fused convert of w1/v1/w2: 2 float4 per thread (32B read / 16B write). nW4 = 2^22.
__global__ void convertW_kernel(const float4* __restrict__ w1, const float4* __restrict__ v1,
                                const float4* __restrict__ w2,
                                uint4* __restrict__ d1, uint4* __restrict__ d2,
                                uint4* __restrict__ d3, int n4) {
    int i = blockIdx.x * blockDim.x + threadIdx.x;      // i in [0, 3*2^21)
    int which = i >> 21;
    int j = (i << 1) & (n4 - 1);                        // even float4 index within section
    const float4* s = (which == 0) ? w1 : (which == 1) ? v1 : w2;
    uint4*        d = (which == 0) ? d1 : (which == 1) ? d2 : d3;
    d[j >> 1] = pack8(s[j], s[j + 1]);
}

__global__ void convertX_kernel(const float4* __restrict__ src, uint4* __restrict__ dst, int n4) {
    int i = blockIdx.x * blockDim.x + threadIdx.x;
    int j = i << 1;
    if (j + 1 < n4) dst[i] = pack8(src[j], src[j + 1]);
}

__global__ void zero_kernel(float4* __restrict__ o, int n4) {
    int i = blockIdx.x * blockDim.x + threadIdx.x;
    if (i < n4) o[i] = make_float4(0.f, 0.f, 0.f, 0.f);
}

// ================= GEMM1: gate/up fused. BM=128, BN=64 (x2 B), BK=32, 4-stage =================
#define G1_STAGE 10240          // halves per stage: As 128*40 + Bw 64*40 + Bv 64*40
#define G1_BWOFF 5120
#define G1_BVOFF 7680
__global__ __launch_bounds__(256) void gemm1_kernel() {
    const int e  = blockIdx.z;
    const int M  = g_cnt[e];
    const int m0 = blockIdx.y * 128;
    if (m0 >= M) return;
    const int n0 = blockIdx.x * 64;

    extern __shared__ __half sm[];
    const int tid = threadIdx.x;

    int    rowA[2]; size_t aoff[2]; bool apred[2];
#pragma unroll
    for (int it = 0; it < 2; it++) {
        int idx = tid + it * 256;
        rowA[it] = idx >> 2;
        int gr = m0 + rowA[it];
        apred[it] = (gr < M);
        aoff[it] = apred[it] ? (size_t)g_tok[e * TT + gr] * HH : 0;
    }
    const int kcA = (tid & 3) * 8;
    const int rowB = tid >> 2;
    const int kcB  = (tid & 3) * 8;
    const size_t boff = ((size_t)e * FF + n0 + rowB) * HH;

    auto load_stage = [&](int s, int kt) {
        __half* st = sm + s * G1_STAGE;
        int k0 = kt * 32;
#pragma unroll
        for (int it = 0; it < 2; it++)
            cp_async16(st + rowA[it] * 40 + kcA, g_xh + aoff[it] + k0 + kcA, apred[it]);
        cp_async16(st + G1_BWOFF + rowB * 40 + kcB, g_w1h + boff + k0 + kcB, true);
        cp_async16(st + G1_BVOFF + rowB * 40 + kcB, g_v1h + boff + k0 + kcB, true);
    };

    const int wid = tid >> 5, lane = tid & 31;
    const int wm = wid >> 1, wn = wid & 1;
    const int g = lane >> 2, tg = lane & 3;

    const int aOff = (lane & 15) * 40 + (lane >> 4) * 8;
    const int bOff = (((lane >> 4) << 3) + (lane & 7)) * 40 + ((lane >> 3) & 1) * 8;

    const uint32_t sBase = (uint32_t)__cvta_generic_to_shared(sm);

    float cg[2][4][4] = {}, cu[2][4][4] = {};

    const int nk = HH / 32;   // 32
#pragma unroll
    for (int p = 0; p < 3; p++) { load_stage(p, p); cp_commit(); }

    for (int kt = 0; kt < nk; kt++) {
        int s = kt & 3;
        cp_wait<2>();
        __syncthreads();
        const uint32_t stg = sBase + s * (G1_STAGE * 2);
#pragma unroll
        for (int k16 = 0; k16 < 32; k16 += 16) {
            uint32_t a[2][4];
            ldsm_x4(a[0], stg + 2 * ((wm * 32)      * 40 + k16 + aOff));
            ldsm_x4(a[1], stg + 2 * ((wm * 32 + 16) * 40 + k16 + aOff));
            uint32_t bw[4][2], bv[4][2];
#pragma unroll
            for (int p = 0; p < 2; p++) {
                uint32_t r[4];
                ldsm_x4(r, stg + 2 * (G1_BWOFF + (wn * 32 + p * 16) * 40 + k16 + bOff));
                bw[2*p][0] = r[0]; bw[2*p][1] = r[1]; bw[2*p+1][0] = r[2]; bw[2*p+1][1] = r[3];
                ldsm_x4(r, stg + 2 * (G1_BVOFF + (wn * 32 + p * 16) * 40 + k16 + bOff));
                bv[2*p][0] = r[0]; bv[2*p][1] = r[1]; bv[2*p+1][0] = r[2]; bv[2*p+1][1] = r[3];
            }
#pragma unroll
            for (int mi = 0; mi < 2; mi++)
#pragma unroll
                for (int ni = 0; ni < 4; ni++) {
                    mma16816(cg[mi][ni], a[mi], bw[ni]);
                    mma16816(cu[mi][ni], a[mi], bv[ni]);
                }
        }
        int nt = kt + 3;
        if (nt < nk) load_stage(nt & 3, nt);
        cp_commit();
    }

    // epilogue: inter = silu(gate) * up
#pragma unroll
    for (int mi = 0; mi < 2; mi++) {
        int rbase = m0 + wm * 32 + mi * 16 + g;
#pragma unroll
        for (int hlf = 0; hlf < 2; hlf++) {
            int r = rbase + hlf * 8;
            if (r >= M) continue;
            size_t ro = ((size_t)e * TT + r) * FF;
#pragma unroll
            for (int ni = 0; ni < 4; ni++) {
                int c = n0 + wn * 32 + ni * 8 + 2 * tg;
                float g0 = cg[mi][ni][hlf * 2 + 0], g1 = cg[mi][ni][hlf * 2 + 1];
                float u0 = cu[mi][ni][hlf * 2 + 0], u1 = cu[mi][ni][hlf * 2 + 1];
                float h0 = g0 / (1.f + __expf(-g0)) * u0;
                float h1 = g1 / (1.f + __expf(-g1)) * u1;
                *(__half2*)&g_inter[ro + c] = __floats2half2_rn(h0, h1);
            }
        }
    }
}

// ================= GEMM2: down-proj. BM=128, BN=128, BK=32, 4-stage + weighted scatter ========
#define B2S 136                 // Bs row stride in halves
#define G2_STAGE 9472           // As 128*40 + Bs 32*136
#define G2_BOFF 5120
__global__ __launch_bounds__(256) void gemm2_kernel(float* __restrict__ out) {
    const int e  = blockIdx.z;
    const int M  = g_cnt[e];
    const int m0 = blockIdx.y * 128;
    if (m0 >= M) return;
    const int n0 = blockIdx.x * 128;

    extern __shared__ __half sm[];
    const int tid = threadIdx.x;
    int rowA[2];
#pragma unroll
    for (int it = 0; it < 2; it++) rowA[it] = (tid + it * 256) >> 2;
    const int kcA = (tid & 3) * 8;
    const size_t abase = ((size_t)e * TT + m0) * FF;
    const size_t bbase = (size_t)e * FF * HH + n0;

    auto load_stage = [&](int s, int kt) {
        __half* st = sm + s * G2_STAGE;
        int k0 = kt * 32;
#pragma unroll
        for (int it = 0; it < 2; it++)
            cp_async16(st + rowA[it] * 40 + kcA, g_inter + abase + (size_t)rowA[it] * FF + k0 + kcA, true);
#pragma unroll
        for (int it = 0; it < 2; it++) {
            int c = tid + it * 256;
            int kr = c >> 4, nc = (c & 15) * 8;
            cp_async16(st + G2_BOFF + kr * B2S + nc, g_w2h + bbase + (size_t)(k0 + kr) * HH + nc, true);
        }
    };

    const int wid = tid >> 5, lane = tid & 31;
    const int wm = wid >> 1, wn = wid & 1;
    const int g = lane >> 2, tg = lane & 3;

    const int aOff  = (lane & 15) * 40 + (lane >> 4) * 8;
    const int bOffT = ((lane & 7) + ((lane >> 3) & 1) * 8) * B2S + (lane >> 4) * 8;

    const uint32_t sBase = (uint32_t)__cvta_generic_to_shared(sm);

    float c[2][8][4] = {};

    const int nk = FF / 32;   // 64
#pragma unroll
    for (int p = 0; p < 3; p++) { load_stage(p, p); cp_commit(); }

    for (int kt = 0; kt < nk; kt++) {
        int s = kt & 3;
        cp_wait<2>();
        __syncthreads();
        const uint32_t stg = sBase + s * (G2_STAGE * 2);
#pragma unroll
        for (int k16 = 0; k16 < 32; k16 += 16) {
            uint32_t a[2][4];
            ldsm_x4(a[0], stg + 2 * ((wm * 32)      * 40 + k16 + aOff));
            ldsm_x4(a[1], stg + 2 * ((wm * 32 + 16) * 40 + k16 + aOff));
            uint32_t b[8][2];
#pragma unroll
            for (int p = 0; p < 4; p++) {
                int ncw = wn * 64 + p * 16;
                uint32_t r[4];
                ldsm_x4_t(r, stg + 2 * (G2_BOFF + k16 * B2S + ncw + bOffT));
                b[2*p][0] = r[0]; b[2*p][1] = r[1]; b[2*p+1][0] = r[2]; b[2*p+1][1] = r[3];
            }
#pragma unroll
            for (int mi = 0; mi < 2; mi++)
#pragma unroll
                for (int ni = 0; ni < 8; ni++)
                    mma16816(c[mi][ni], a[mi], b[ni]);
        }
        int nt = kt + 3;
        if (nt < nk) load_stage(nt & 3, nt);
        cp_commit();
    }

    // epilogue: out[token] += cw * down
#pragma unroll
    for (int mi = 0; mi < 2; mi++) {
        int rbase = m0 + wm * 32 + mi * 16 + g;
#pragma unroll
        for (int hlf = 0; hlf < 2; hlf++) {
            int r = rbase + hlf * 8;
            if (r >= M) continue;
            int   t = g_tok[e * TT + r];
            float w = g_cw[e * TT + r];
            float* orow = out + (size_t)t * HH;
#pragma unroll
            for (int ni = 0; ni < 8; ni++) {
                int h = n0 + wn * 64 + ni * 8 + 2 * tg;
                atomicAdd(&orow[h],     w * c[mi][ni][hlf * 2 + 0]);
                atomicAdd(&orow[h + 1], w * c[mi][ni][hlf * 2 + 1]);
            }
        }
    }
}

// ---------------- launch ----------------
extern "C" void kernel_launch(void* const* d_in, const int* in_sizes, int n_in,
                              void* d_out, int out_size) {
    const float* x  = (const float*)d_in[0];
    const float* tw = (const float*)d_in[2];
    const void*  te = d_in[3];
    const float* w1 = (const float*)d_in[4];
    const float* v1 = (const float*)d_in[5];
    const float* w2 = (const float*)d_in[6];
    float* out = (float*)d_out;

    void *pxh, *pw1, *pv1, *pw2;
    cudaGetSymbolAddress(&pxh, g_xh);
    cudaGetSymbolAddress(&pw1, g_w1h);
    cudaGetSymbolAddress(&pv1, g_v1h);
    cudaGetSymbolAddress(&pw2, g_w2h);

    const int g1_smem = 4 * G1_STAGE * 2;   // 81920 B
    const int g2_smem = 4 * G2_STAGE * 2;   // 75776 B
    cudaFuncSetAttribute(gemm1_kernel, cudaFuncAttributeMaxDynamicSharedMemorySize, g1_smem);
    cudaFuncSetAttribute(gemm2_kernel, cudaFuncAttributeMaxDynamicSharedMemorySize, g2_smem);

    detect_zero_kernel<<<1, 256>>>((const unsigned int*)te);
    gather_kernel<<<TT / 256, 256>>>(tw, (const int*)te);

    const int nW4 = (EE * FF * HH) / 4;   // 2^22
    convertW_kernel<<<(3 * nW4 / 2) / 256, 256>>>((const float4*)w1, (const float4*)v1, (const float4*)w2,
                                                  (uint4*)pw1, (uint4*)pv1, (uint4*)pw2, nW4);
    const int nX4 = (TT * HH) / 4;        // 2^19
    convertX_kernel<<<(nX4 / 2) / 256, 256>>>((const float4*)x, (uint4*)pxh, nX4);

    zero_kernel<<<(out_size / 4 + 255) / 256, 256>>>((float4*)d_out, out_size / 4);

    gemm1_kernel<<<dim3(FF / 64, TT / 128, EE), 256, g1_smem>>>();
    gemm2_kernel<<<dim3(HH / 128, TT / 128, EE), 256, g2_smem>>>(out);
}